// round 13
// baseline (speedup 1.0000x reference)
#include <cuda_runtime.h>
#include <cuda_bf16.h>
#include <cstdint>
#include <math.h>

#define T_STEPS 1024
#define BATCH   64
#define UDIM    256
#define FDIM    128
#define NB      4      // batches per cluster (pipeline depth)

// 64MB scratch for h[b][t][u] (device global: allowed, no runtime alloc)
__device__ float g_h[(size_t)BATCH * T_STEPS * UDIM];

// ---------------- helpers ----------------
__device__ __forceinline__ void fma2(unsigned long long &d, unsigned long long a, unsigned long long b) {
    asm("fma.rn.f32x2 %0, %1, %2, %0;" : "+l"(d) : "l"(a), "l"(b));
}
__device__ __forceinline__ float lo32(unsigned long long v){ return __uint_as_float((unsigned)(v & 0xffffffffull)); }
__device__ __forceinline__ float hi32(unsigned long long v){ return __uint_as_float((unsigned)(v >> 32)); }
__device__ __forceinline__ unsigned long long packf2(float lo, float hi){
    return (unsigned long long)__float_as_uint(lo) | ((unsigned long long)__float_as_uint(hi) << 32);
}
__device__ __forceinline__ uint32_t smem_u32(const void* p) {
    return (uint32_t)__cvta_generic_to_shared(p);
}
__device__ __forceinline__ uint32_t mapa_u32(uint32_t a, uint32_t peer) {
    uint32_t d;
    asm("mapa.shared::cluster.u32 %0, %1, %2;" : "=r"(d) : "r"(a), "r"(peer));
    return d;
}
__device__ __forceinline__ void mbar_init(uint32_t addr, uint32_t count) {
    asm volatile("mbarrier.init.shared.b64 [%0], %1;" :: "r"(addr), "r"(count) : "memory");
}
__device__ __forceinline__ void mbar_arrive_plain(uint32_t addr) {
    asm volatile("mbarrier.arrive.shared::cta.b64 _, [%0];" :: "r"(addr) : "memory");
}
__device__ __forceinline__ void mbar_expect_tx(uint32_t addr, uint32_t bytes) {
    asm volatile("mbarrier.arrive.expect_tx.shared::cta.b64 _, [%0], %1;"
                 :: "r"(addr), "r"(bytes) : "memory");
}
// cta-scope acquire: st.async deliveries complete at the destination smem
// before the tx counts, so cluster-scope acquire is unnecessary.
__device__ __forceinline__ void mbar_wait(uint32_t addr, uint32_t parity) {
    asm volatile(
        "{\n\t"
        ".reg .pred P;\n\t"
        "WAIT_%=:\n\t"
        "mbarrier.try_wait.parity.acquire.cta.shared::cta.b64 P, [%0], %1, 0x989680;\n\t"
        "@P bra DONE_%=;\n\t"
        "bra WAIT_%=;\n\t"
        "DONE_%=:\n\t"
        "}"
        :: "r"(addr), "r"(parity) : "memory");
}
// fused data+signal: store 4B into (cluster) smem and complete_tx on the
// mbarrier co-located in the SAME destination CTA. One transaction.
__device__ __forceinline__ void st_async_f32(uint32_t daddr, float v, uint32_t dmbar) {
    asm volatile("st.async.shared::cluster.mbarrier::complete_tx::bytes.f32 [%0], %1, [%2];"
                 :: "r"(daddr), "f"(v), "r"(dmbar) : "memory");
}
// branchless tanh: 1 - 2/(exp(2x)+1), ex2.approx + rcp.approx (~1e-7 abs err)
__device__ __forceinline__ float fast_tanh(float x) {
    float z = x * 2.8853900817779268f;   // 2*log2(e)
    float e;
    asm("ex2.approx.f32 %0, %1;" : "=f"(e) : "f"(z));
    float d = e + 1.0f;
    float r;
    asm("rcp.approx.f32 %0, %1;" : "=f"(r) : "f"(d));
    return fmaf(-2.0f, r, 1.0f);
}

// state buffer layout: quarter q (64 cols) padded by 16B so the 4 per-warp
// broadcast groups (one per K-quarter) hit disjoint bank sets.
#define SBUF_STRIDE 272
#define PAR_STRIDE  (SBUF_STRIDE * 4)        // bytes per parity slot (1088)
#define BAT_STRIDE  (2 * SBUF_STRIDE * 4)    // bytes per batch (2176)
__device__ __forceinline__ int sidx4(int c){ return c + ((c >> 6) << 2); }

// ============================================================
// Phase 1: g_h[b][t][u] = sum_f inputs[b,t,f] * R[f,u]
// ============================================================
__global__ __launch_bounds__(256)
void p1_gemm(const float* __restrict__ x, const float* __restrict__ R) {
    extern __shared__ unsigned char smraw[];
    float* xs = (float*)smraw;                                          // 32KB
    unsigned long long* Rp = (unsigned long long*)(smraw + 64*128*4);   // 64KB

    const int tid = threadIdx.x;
    const int c = blockIdx.x;
    const int rowblk = c >> 1, uh = c & 1;
    const int m0 = rowblk * 64, ub = uh * 128;

    {
        const float4* xg = (const float4*)(x + (size_t)m0 * FDIM);
        float4* xs4 = (float4*)xs;
        #pragma unroll
        for (int i = 0; i < 8; i++) xs4[tid + 256*i] = xg[tid + 256*i];
    }
    for (int i = tid; i < 64*128; i += 256) {
        int k2 = i >> 7; int u = (i & 127) + ub;
        Rp[i] = packf2(R[(size_t)(2*k2) * UDIM + u], R[(size_t)(2*k2+1) * UDIM + u]);
    }
    __syncthreads();

    const int cg = tid & 31, tr = tid >> 5;
    const int u0 = cg * 4, r0 = tr * 8;

    unsigned long long acc[8][4];
    #pragma unroll
    for (int a = 0; a < 8; a++)
        #pragma unroll
        for (int bb = 0; bb < 4; bb++) acc[a][bb] = 0ULL;

    #pragma unroll 8
    for (int k2 = 0; k2 < 64; k2++) {
        const ulonglong2* rp2 = (const ulonglong2*)(Rp + k2*128 + u0);
        ulonglong2 v0 = rp2[0], v1 = rp2[1];
        #pragma unroll
        for (int rr = 0; rr < 8; rr++) {
            unsigned long long xp = *(const unsigned long long*)(xs + (r0+rr)*FDIM + 2*k2);
            fma2(acc[rr][0], xp, v0.x);
            fma2(acc[rr][1], xp, v0.y);
            fma2(acc[rr][2], xp, v1.x);
            fma2(acc[rr][3], xp, v1.y);
        }
    }

    #pragma unroll
    for (int rr = 0; rr < 8; rr++) {
        int m = m0 + r0 + rr;   // m = b*1024 + t -> [B][T][U] directly
        float4 o;
        o.x = lo32(acc[rr][0]) + hi32(acc[rr][0]);
        o.y = lo32(acc[rr][1]) + hi32(acc[rr][1]);
        o.z = lo32(acc[rr][2]) + hi32(acc[rr][2]);
        o.w = lo32(acc[rr][3]) + hi32(acc[rr][3]);
        *(float4*)(g_h + (size_t)m * UDIM + ub + u0) = o;
    }
}

// ============================================================
// Phase 2: recurrence, 4-batch SOFTWARE PIPELINE.
// 16 clusters x 2 CTAs; cluster c handles batches 4c..4c+3 (lockstep phases).
// One mbarrier per batch. Per iteration, for bb = 0..3:
//   wait[bb](t&1) -> expect[bb] -> compute bb -> fire bb (st.async fused tx)
//   -> output STGs for bb.
// Each batch's cluster transit hides behind the other THREE batches' compute.
// Addressing is base + ALU offset (bb*BAT_STRIDE + parity*PAR_STRIDE) to keep
// register count under the 255 ceiling.
// ============================================================
__global__ __launch_bounds__(256, 1) __cluster_dims__(2, 1, 1)
void p2_rnn(const float* __restrict__ W, const float* __restrict__ bias,
            const float* __restrict__ x0, float* __restrict__ out) {
    __shared__ __align__(16) float sbuf[NB][2][SBUF_STRIDE];  // [batch][parity][state]
    __shared__ __align__(8) unsigned long long mbar[NB];

    const int tid  = threadIdx.x;
    uint32_t rank;
    asm("mov.u32 %0, %%cluster_ctarank;" : "=r"(rank));
    const int c    = blockIdx.x >> 1;       // cluster index
    const int bb0  = NB * c;                // first batch of this cluster
    const int w    = tid >> 5;
    const int l    = tid & 31;
    const int jA   = w * 16 + (l & 7);
    const int jgA  = (int)rank * 128 + jA;
    const int jgB  = jgA + 8;
    const int k0   = (l >> 3) * 64;

    // W segments for 2 columns x quarter-K, packed f32x2: 64 u64 = 128 regs
    unsigned long long wpA[32], wpB[32];
    #pragma unroll
    for (int m = 0; m < 32; m++) {
        wpA[m] = packf2(W[(size_t)(k0 + 2*m)     * UDIM + jgA],
                        W[(size_t)(k0 + 2*m + 1) * UDIM + jgA]);
        wpB[m] = packf2(W[(size_t)(k0 + 2*m)     * UDIM + jgB],
                        W[(size_t)(k0 + 2*m + 1) * UDIM + jgB]);
    }

    // single base pointers; per-batch offsets fold into immediates
    const float* hbA = g_h + (size_t)bb0 * T_STEPS * UDIM + jgA;   // + bb*T*U + t*U
    const float* hbB = hbA + 8;
    float* obA = out + (size_t)bb0 * UDIM + jgA;                   // + bb*U + t*B*U
    float* obB = obA + 8;
    const float biasA = bias[jgA];
    const float biasB = bias[jgB];

    // h pipelines per batch: {cur, next}
    float h0A[NB], h1A[NB], h0B[NB], h1B[NB];
    #pragma unroll
    for (int bb = 0; bb < NB; bb++) {
        const size_t o = (size_t)bb * T_STEPS * UDIM;
        h0A[bb] = hbA[o];         h1A[bb] = hbA[o + UDIM];
        h0B[bb] = hbB[o];         h1B[bb] = hbB[o + UDIM];
    }

    if (tid < UDIM) {
        float v = x0[tid];
        #pragma unroll
        for (int bb = 0; bb < NB; bb++) sbuf[bb][0][sidx4(tid)] = v;
    }
    if (tid == 0) {
        #pragma unroll
        for (int bb = 0; bb < NB; bb++) {
            mbar_init(smem_u32(&mbar[bb]), 1);
            mbar_arrive_plain(smem_u32(&mbar[bb]));   // complete phase 0
        }
    }
    __syncthreads();
    asm volatile("barrier.cluster.arrive.aligned;" ::: "memory");
    asm volatile("barrier.cluster.wait.aligned;"   ::: "memory");

    const uint32_t pr      = rank ^ 1u;
    const uint32_t mb_loc  = smem_u32(&mbar[0]);           // + 8*bb
    const uint32_t mb_own  = mapa_u32(mb_loc, rank);
    const uint32_t mb_peer = mapa_u32(mb_loc, pr);
    const uint32_t sb_own  = mapa_u32(smem_u32(&sbuf[0][0][0]), rank);
    const uint32_t sb_peer = mapa_u32(smem_u32(&sbuf[0][0][0]), pr);
    const uint32_t offA = (uint32_t)sidx4(jgA) * 4u;
    const uint32_t offB = (uint32_t)sidx4(jgB) * 4u;

    for (int t = 0; t < T_STEPS; t++) {
        const int p = t & 1, np = p ^ 1;
        const uint32_t par = (uint32_t)(t & 1);
        const size_t oo = (size_t)t * BATCH * UDIM;

        // prefetch h for t+2 (independent of the chain)
        float h2A[NB], h2B[NB];
        if (t + 2 < T_STEPS) {
            #pragma unroll
            for (int bb = 0; bb < NB; bb++) {
                const size_t o = (size_t)bb * T_STEPS * UDIM + (size_t)(t + 2) * UDIM;
                h2A[bb] = __ldcs(hbA + o);
                h2B[bb] = __ldcs(hbB + o);
            }
        } else {
            #pragma unroll
            for (int bb = 0; bb < NB; bb++) { h2A[bb] = 0.f; h2B[bb] = 0.f; }
        }

        #pragma unroll
        for (int bb = 0; bb < NB; bb++) {
            const uint32_t ml = mb_loc + 8u * bb;
            mbar_wait(ml, par);                       // batch bb, phase t
            if (tid == 0) mbar_expect_tx(ml, 1024);   // arm phase t+1

            const float* sb = &sbuf[bb][p][sidx4(k0)];
            unsigned long long aA0 = 0ULL, aA1 = 0ULL, aB0 = 0ULL, aB1 = 0ULL;
            #pragma unroll
            for (int i = 0; i < 8; i++) {
                ulonglong2 s0 = *(const ulonglong2*)(sb + 8*i);
                ulonglong2 s1 = *(const ulonglong2*)(sb + 8*i + 4);
                fma2(aA0, s0.x, wpA[4*i + 0]);
                fma2(aB0, s0.x, wpB[4*i + 0]);
                fma2(aA1, s0.y, wpA[4*i + 1]);
                fma2(aB1, s0.y, wpB[4*i + 1]);
                fma2(aA0, s1.x, wpA[4*i + 2]);
                fma2(aB0, s1.x, wpB[4*i + 2]);
                fma2(aA1, s1.y, wpA[4*i + 3]);
                fma2(aB1, s1.y, wpB[4*i + 3]);
            }
            float pA = (lo32(aA0) + hi32(aA0)) + (lo32(aA1) + hi32(aA1));
            float pB = (lo32(aB0) + hi32(aB0)) + (lo32(aB1) + hi32(aB1));
            pA += __shfl_xor_sync(0xffffffffu, pA, 8);
            pB += __shfl_xor_sync(0xffffffffu, pB, 8);
            pA += __shfl_xor_sync(0xffffffffu, pA, 16);
            pB += __shfl_xor_sync(0xffffffffu, pB, 16);
            const float valA = fast_tanh(h0A[bb] + pA + biasA);
            const float valB = fast_tanh(h0B[bb] + pB + biasB);

            const uint32_t soff = (uint32_t)(bb * BAT_STRIDE) + (uint32_t)np * PAR_STRIDE;
            if (l < 8) {
                const uint32_t ob = sb_own + soff;
                st_async_f32(ob + offA, valA, mb_own + 8u * bb);
                st_async_f32(ob + offB, valB, mb_own + 8u * bb);
            } else if (l < 16) {
                const uint32_t pb = sb_peer + soff;
                st_async_f32(pb + offA, valA, mb_peer + 8u * bb);
                st_async_f32(pb + offB, valB, mb_peer + 8u * bb);
            } else if (l < 24) {
                obA[oo + (size_t)bb * UDIM] = valA;   // [T][B][U]
            } else {
                obB[oo + (size_t)bb * UDIM] = valB;
            }

            h0A[bb] = h1A[bb]; h1A[bb] = h2A[bb];
            h0B[bb] = h1B[bb]; h1B[bb] = h2B[bb];
        }
    }

    asm volatile("barrier.cluster.arrive.aligned;" ::: "memory");
    asm volatile("barrier.cluster.wait.aligned;"   ::: "memory");
}

extern "C" void kernel_launch(void* const* d_in, const int* in_sizes, int n_in,
                              void* d_out, int out_size) {
    const float* x    = (const float*)d_in[0];  // [B, T, F]
    const float* R    = (const float*)d_in[1];  // [F, U]
    const float* W    = (const float*)d_in[2];  // [U, U]
    const float* bias = (const float*)d_in[3];  // [U]
    const float* x0   = (const float*)d_in[4];  // [U]
    float* out = (float*)d_out;                 // [T, B, U]

    cudaFuncSetAttribute(p1_gemm, cudaFuncAttributeMaxDynamicSharedMemorySize, 98304);
    p1_gemm<<<2048, 256, 98304>>>(x, R);
    p2_rnn<<<(BATCH / NB) * 2, 256>>>(W, bias, x0, out);
}

// round 14
// speedup vs baseline: 1.6352x; 1.6352x over previous
#include <cuda_runtime.h>
#include <cuda_bf16.h>
#include <cstdint>
#include <math.h>

#define T_STEPS 1024
#define BATCH   64
#define UDIM    256
#define FDIM    128
#define NB      2      // batches per cluster (proven best depth)
#define CSZ     4      // cluster size (CTAs per cluster)

// 64MB scratch for h[b][t][u] (device global: allowed, no runtime alloc)
__device__ float g_h[(size_t)BATCH * T_STEPS * UDIM];

// ---------------- helpers ----------------
__device__ __forceinline__ void fma2(unsigned long long &d, unsigned long long a, unsigned long long b) {
    asm("fma.rn.f32x2 %0, %1, %2, %0;" : "+l"(d) : "l"(a), "l"(b));
}
__device__ __forceinline__ float lo32(unsigned long long v){ return __uint_as_float((unsigned)(v & 0xffffffffull)); }
__device__ __forceinline__ float hi32(unsigned long long v){ return __uint_as_float((unsigned)(v >> 32)); }
__device__ __forceinline__ unsigned long long packf2(float lo, float hi){
    return (unsigned long long)__float_as_uint(lo) | ((unsigned long long)__float_as_uint(hi) << 32);
}
__device__ __forceinline__ uint32_t smem_u32(const void* p) {
    return (uint32_t)__cvta_generic_to_shared(p);
}
__device__ __forceinline__ uint32_t mapa_u32(uint32_t a, uint32_t peer) {
    uint32_t d;
    asm("mapa.shared::cluster.u32 %0, %1, %2;" : "=r"(d) : "r"(a), "r"(peer));
    return d;
}
__device__ __forceinline__ void mbar_init(uint32_t addr, uint32_t count) {
    asm volatile("mbarrier.init.shared.b64 [%0], %1;" :: "r"(addr), "r"(count) : "memory");
}
__device__ __forceinline__ void mbar_arrive_plain(uint32_t addr) {
    asm volatile("mbarrier.arrive.shared::cta.b64 _, [%0];" :: "r"(addr) : "memory");
}
__device__ __forceinline__ void mbar_expect_tx(uint32_t addr, uint32_t bytes) {
    asm volatile("mbarrier.arrive.expect_tx.shared::cta.b64 _, [%0], %1;"
                 :: "r"(addr), "r"(bytes) : "memory");
}
// cta-scope acquire: st.async deliveries complete at the destination smem
// before the tx counts, so cluster-scope acquire is unnecessary.
__device__ __forceinline__ void mbar_wait(uint32_t addr, uint32_t parity) {
    asm volatile(
        "{\n\t"
        ".reg .pred P;\n\t"
        "WAIT_%=:\n\t"
        "mbarrier.try_wait.parity.acquire.cta.shared::cta.b64 P, [%0], %1, 0x989680;\n\t"
        "@P bra DONE_%=;\n\t"
        "bra WAIT_%=;\n\t"
        "DONE_%=:\n\t"
        "}"
        :: "r"(addr), "r"(parity) : "memory");
}
// fused data+signal: store 4B into (cluster) smem and complete_tx on the
// mbarrier co-located in the SAME destination CTA. One transaction.
__device__ __forceinline__ void st_async_f32(uint32_t daddr, float v, uint32_t dmbar) {
    asm volatile("st.async.shared::cluster.mbarrier::complete_tx::bytes.f32 [%0], %1, [%2];"
                 :: "r"(daddr), "f"(v), "r"(dmbar) : "memory");
}
// branchless tanh: 1 - 2/(exp(2x)+1), ex2.approx + rcp.approx (~1e-7 abs err)
__device__ __forceinline__ float fast_tanh(float x) {
    float z = x * 2.8853900817779268f;   // 2*log2(e)
    float e;
    asm("ex2.approx.f32 %0, %1;" : "=f"(e) : "f"(z));
    float d = e + 1.0f;
    float r;
    asm("rcp.approx.f32 %0, %1;" : "=f"(r) : "f"(d));
    return fmaf(-2.0f, r, 1.0f);
}

// state buffer layout: quarter q (64 cols) padded by 16B so the 4 per-warp
// broadcast groups (one per K-quarter) hit disjoint bank sets.
#define SBUF_STRIDE 272
__device__ __forceinline__ int sidx4(int c){ return c + ((c >> 6) << 2); }

// ============================================================
// Phase 1: g_h[b][t][u] = sum_f inputs[b,t,f] * R[f,u]
// ============================================================
__global__ __launch_bounds__(256)
void p1_gemm(const float* __restrict__ x, const float* __restrict__ R) {
    extern __shared__ unsigned char smraw[];
    float* xs = (float*)smraw;                                          // 32KB
    unsigned long long* Rp = (unsigned long long*)(smraw + 64*128*4);   // 64KB

    const int tid = threadIdx.x;
    const int c = blockIdx.x;
    const int rowblk = c >> 1, uh = c & 1;
    const int m0 = rowblk * 64, ub = uh * 128;

    {
        const float4* xg = (const float4*)(x + (size_t)m0 * FDIM);
        float4* xs4 = (float4*)xs;
        #pragma unroll
        for (int i = 0; i < 8; i++) xs4[tid + 256*i] = xg[tid + 256*i];
    }
    for (int i = tid; i < 64*128; i += 256) {
        int k2 = i >> 7; int u = (i & 127) + ub;
        Rp[i] = packf2(R[(size_t)(2*k2) * UDIM + u], R[(size_t)(2*k2+1) * UDIM + u]);
    }
    __syncthreads();

    const int cg = tid & 31, tr = tid >> 5;
    const int u0 = cg * 4, r0 = tr * 8;

    unsigned long long acc[8][4];
    #pragma unroll
    for (int a = 0; a < 8; a++)
        #pragma unroll
        for (int bb = 0; bb < 4; bb++) acc[a][bb] = 0ULL;

    #pragma unroll 8
    for (int k2 = 0; k2 < 64; k2++) {
        const ulonglong2* rp2 = (const ulonglong2*)(Rp + k2*128 + u0);
        ulonglong2 v0 = rp2[0], v1 = rp2[1];
        #pragma unroll
        for (int rr = 0; rr < 8; rr++) {
            unsigned long long xp = *(const unsigned long long*)(xs + (r0+rr)*FDIM + 2*k2);
            fma2(acc[rr][0], xp, v0.x);
            fma2(acc[rr][1], xp, v0.y);
            fma2(acc[rr][2], xp, v1.x);
            fma2(acc[rr][3], xp, v1.y);
        }
    }

    #pragma unroll
    for (int rr = 0; rr < 8; rr++) {
        int m = m0 + r0 + rr;   // m = b*1024 + t -> [B][T][U] directly
        float4 o;
        o.x = lo32(acc[rr][0]) + hi32(acc[rr][0]);
        o.y = lo32(acc[rr][1]) + hi32(acc[rr][1]);
        o.z = lo32(acc[rr][2]) + hi32(acc[rr][2]);
        o.w = lo32(acc[rr][3]) + hi32(acc[rr][3]);
        *(float4*)(g_h + (size_t)m * UDIM + ub + u0) = o;
    }
}

// ============================================================
// Phase 2: recurrence. 16 clusters x 4 CTAs (128 CTAs); cluster c handles
// batches 2c, 2c+1 in a 2-deep software pipeline (R12 structure, proven).
// Wait — batches: 64 / 2 = 32 clusters x 4 CTAs = 128 CTAs.
// CTA rank r owns output columns [r*64, r*64+64), FULL K=256 in registers
// (64 regs as 32 u64 f32x2 pairs per thread).
// Thread map (warp w=0..7, lane l): col jloc = w*8 + (l&7), quarter q = l>>3,
// K range [q*64, q*64+64). 8 LDS.128 -> 32 FFMA2 per thread per batch-step.
// Reduce over q: shfl.xor(8) + shfl.xor(16); all 4 q-lanes hold the sum.
// Exchange: lane q ships its column's value to CTA q via one fused st.async
// (data + complete_tx on CTA q's per-batch mbarrier). Each CTA receives the
// full 256-state (64 cols from each of 4 CTAs) = 1024B tx per batch.
// The q == (rank+2)&3 lane additionally does the output STG.
// Pipeline: wait_b0 -> arm -> compute b0 -> fire b0 -> wait_b1 -> arm ->
// compute b1 -> fire b1. Parity = t&1, phase-0 bootstrapped by a plain arrive.
// ============================================================
__global__ __launch_bounds__(256, 1) __cluster_dims__(CSZ, 1, 1)
void p2_rnn(const float* __restrict__ W, const float* __restrict__ bias,
            const float* __restrict__ x0, float* __restrict__ out) {
    __shared__ __align__(16) float sbuf[NB][2][SBUF_STRIDE];  // [batch][parity][state]
    __shared__ __align__(8) unsigned long long mbar[NB];

    const int tid  = threadIdx.x;
    uint32_t rank;
    asm("mov.u32 %0, %%cluster_ctarank;" : "=r"(rank));
    const int c    = blockIdx.x / CSZ;      // cluster index
    const int b0   = 2 * c, b1 = 2 * c + 1;
    const int w    = tid >> 5;
    const int l    = tid & 31;
    const uint32_t q = (uint32_t)(l >> 3);  // K-quarter AND destination CTA
    const int jg   = (int)rank * 64 + w * 8 + (l & 7);   // global output column
    const int k0   = (int)q * 64;

    // W column segment, full-K split by quarter: 32 u64 = 64 regs
    unsigned long long wp[32];
    #pragma unroll
    for (int m = 0; m < 32; m++) {
        wp[m] = packf2(W[(size_t)(k0 + 2*m)     * UDIM + jg],
                       W[(size_t)(k0 + 2*m + 1) * UDIM + jg]);
    }

    const float* hp0 = g_h + (size_t)b0 * T_STEPS * UDIM + jg;
    const float* hp1 = g_h + (size_t)b1 * T_STEPS * UDIM + jg;
    float* ob0 = out + (size_t)b0 * UDIM + jg;
    float* ob1 = out + (size_t)b1 * UDIM + jg;
    const float bias_j = bias[jg];
    float h0_0 = hp0[0], h1_0 = hp0[UDIM];
    float h0_1 = hp1[0], h1_1 = hp1[UDIM];

    if (tid < UDIM) {
        float v = x0[tid];
        #pragma unroll
        for (int bb = 0; bb < NB; bb++) sbuf[bb][0][sidx4(tid)] = v;
    }
    if (tid == 0) {
        #pragma unroll
        for (int bb = 0; bb < NB; bb++) {
            mbar_init(smem_u32(&mbar[bb]), 1);
            mbar_arrive_plain(smem_u32(&mbar[bb]));   // complete phase 0
        }
    }
    __syncthreads();
    asm volatile("barrier.cluster.arrive.aligned;" ::: "memory");
    asm volatile("barrier.cluster.wait.aligned;"   ::: "memory");

    const uint32_t m0loc = smem_u32(&mbar[0]);
    const uint32_t m1loc = smem_u32(&mbar[1]);
    // destination = CTA q (this lane's quarter). One mapa each for mbar + sbuf.
    const uint32_t dmb0 = mapa_u32(m0loc, q);
    const uint32_t dmb1 = mapa_u32(m1loc, q);
    const uint32_t dsb  = mapa_u32(smem_u32(&sbuf[0][0][0]), q);
    const uint32_t doff = (uint32_t)sidx4(jg) * 4u;
    const bool do_out = (q == ((rank + 2u) & 3u));
    // byte offsets of sbuf[bb][par] from sbuf base
    const uint32_t PAR_B = SBUF_STRIDE * 4u;
    const uint32_t BAT_B = 2u * PAR_B;

    for (int t = 0; t < T_STEPS; t++) {
        const int p = t & 1;
        const uint32_t np = (uint32_t)(p ^ 1);
        const uint32_t par = (uint32_t)(t & 1);

        // prefetch h for t+2 (independent of the chain)
        float h2_0 = 0.f, h2_1 = 0.f;
        if (t + 2 < T_STEPS) {
            h2_0 = __ldcs(hp0 + (size_t)(t + 2) * UDIM);
            h2_1 = __ldcs(hp1 + (size_t)(t + 2) * UDIM);
        }

        // ---------- batch 0 ----------
        mbar_wait(m0loc, par);
        if (tid == 0) mbar_expect_tx(m0loc, 1024);
        float val0;
        {
            const float* sb = &sbuf[0][p][sidx4(k0)];
            unsigned long long a0 = 0ULL, a1 = 0ULL, a2 = 0ULL, a3 = 0ULL;
            #pragma unroll
            for (int i = 0; i < 8; i++) {
                ulonglong2 s0 = *(const ulonglong2*)(sb + 8*i);
                ulonglong2 s1 = *(const ulonglong2*)(sb + 8*i + 4);
                fma2(a0, s0.x, wp[4*i + 0]);
                fma2(a1, s0.y, wp[4*i + 1]);
                fma2(a2, s1.x, wp[4*i + 2]);
                fma2(a3, s1.y, wp[4*i + 3]);
            }
            float pa = ((lo32(a0) + hi32(a0)) + (lo32(a1) + hi32(a1)))
                     + ((lo32(a2) + hi32(a2)) + (lo32(a3) + hi32(a3)));
            pa += __shfl_xor_sync(0xffffffffu, pa, 8);
            pa += __shfl_xor_sync(0xffffffffu, pa, 16);
            val0 = fast_tanh(h0_0 + pa + bias_j);
        }
        // every lane ships its column value to CTA q (fused data+tx)
        st_async_f32(dsb + np * PAR_B + doff, val0, dmb0);

        // ---------- batch 1 ----------
        mbar_wait(m1loc, par);
        if (tid == 0) mbar_expect_tx(m1loc, 1024);
        float val1;
        {
            const float* sb = &sbuf[1][p][sidx4(k0)];
            unsigned long long a0 = 0ULL, a1 = 0ULL, a2 = 0ULL, a3 = 0ULL;
            #pragma unroll
            for (int i = 0; i < 8; i++) {
                ulonglong2 s0 = *(const ulonglong2*)(sb + 8*i);
                ulonglong2 s1 = *(const ulonglong2*)(sb + 8*i + 4);
                fma2(a0, s0.x, wp[4*i + 0]);
                fma2(a1, s0.y, wp[4*i + 1]);
                fma2(a2, s1.x, wp[4*i + 2]);
                fma2(a3, s1.y, wp[4*i + 3]);
            }
            float pa = ((lo32(a0) + hi32(a0)) + (lo32(a1) + hi32(a1)))
                     + ((lo32(a2) + hi32(a2)) + (lo32(a3) + hi32(a3)));
            pa += __shfl_xor_sync(0xffffffffu, pa, 8);
            pa += __shfl_xor_sync(0xffffffffu, pa, 16);
            val1 = fast_tanh(h0_1 + pa + bias_j);
        }
        st_async_f32(dsb + BAT_B + np * PAR_B + doff, val1, dmb1);

        // outputs [T][B][U], one lane per column, off the inter-CTA chain
        if (do_out) {
            ob0[(size_t)t * BATCH * UDIM] = val0;
            ob1[(size_t)t * BATCH * UDIM] = val1;
        }

        h0_0 = h1_0; h1_0 = h2_0;
        h0_1 = h1_1; h1_1 = h2_1;
    }

    asm volatile("barrier.cluster.arrive.aligned;" ::: "memory");
    asm volatile("barrier.cluster.wait.aligned;"   ::: "memory");
}

extern "C" void kernel_launch(void* const* d_in, const int* in_sizes, int n_in,
                              void* d_out, int out_size) {
    const float* x    = (const float*)d_in[0];  // [B, T, F]
    const float* R    = (const float*)d_in[1];  // [F, U]
    const float* W    = (const float*)d_in[2];  // [U, U]
    const float* bias = (const float*)d_in[3];  // [U]
    const float* x0   = (const float*)d_in[4];  // [U]
    float* out = (float*)d_out;                 // [T, B, U]

    cudaFuncSetAttribute(p1_gemm, cudaFuncAttributeMaxDynamicSharedMemorySize, 98304);
    p1_gemm<<<2048, 256, 98304>>>(x, R);
    p2_rnn<<<(BATCH / NB) * CSZ, 256>>>(W, bias, x0, out);
}

// round 15
// speedup vs baseline: 2.0708x; 1.2664x over previous
#include <cuda_runtime.h>
#include <cuda_bf16.h>
#include <cstdint>
#include <math.h>

#define T_STEPS 1024
#define BATCH   64
#define UDIM    256
#define FDIM    128

// 64MB scratch for h[b][t][u] (device global: allowed, no runtime alloc)
__device__ float g_h[(size_t)BATCH * T_STEPS * UDIM];

// ---------------- helpers ----------------
__device__ __forceinline__ void fma2(unsigned long long &d, unsigned long long a, unsigned long long b) {
    asm("fma.rn.f32x2 %0, %1, %2, %0;" : "+l"(d) : "l"(a), "l"(b));
}
__device__ __forceinline__ float lo32(unsigned long long v){ return __uint_as_float((unsigned)(v & 0xffffffffull)); }
__device__ __forceinline__ float hi32(unsigned long long v){ return __uint_as_float((unsigned)(v >> 32)); }
__device__ __forceinline__ unsigned long long packf2(float lo, float hi){
    return (unsigned long long)__float_as_uint(lo) | ((unsigned long long)__float_as_uint(hi) << 32);
}
__device__ __forceinline__ uint32_t smem_u32(const void* p) {
    return (uint32_t)__cvta_generic_to_shared(p);
}
__device__ __forceinline__ uint32_t mapa_u32(uint32_t a, uint32_t peer) {
    uint32_t d;
    asm("mapa.shared::cluster.u32 %0, %1, %2;" : "=r"(d) : "r"(a), "r"(peer));
    return d;
}
__device__ __forceinline__ void mbar_init(uint32_t addr, uint32_t count) {
    asm volatile("mbarrier.init.shared.b64 [%0], %1;" :: "r"(addr), "r"(count) : "memory");
}
__device__ __forceinline__ void mbar_arrive_plain(uint32_t addr) {
    asm volatile("mbarrier.arrive.shared::cta.b64 _, [%0];" :: "r"(addr) : "memory");
}
__device__ __forceinline__ void mbar_expect_tx(uint32_t addr, uint32_t bytes) {
    asm volatile("mbarrier.arrive.expect_tx.shared::cta.b64 _, [%0], %1;"
                 :: "r"(addr), "r"(bytes) : "memory");
}
// cta-scope acquire: st.async deliveries complete at the destination smem
// before the tx counts, so cluster-scope acquire is unnecessary.
__device__ __forceinline__ void mbar_wait(uint32_t addr, uint32_t parity) {
    asm volatile(
        "{\n\t"
        ".reg .pred P;\n\t"
        "WAIT_%=:\n\t"
        "mbarrier.try_wait.parity.acquire.cta.shared::cta.b64 P, [%0], %1, 0x989680;\n\t"
        "@P bra DONE_%=;\n\t"
        "bra WAIT_%=;\n\t"
        "DONE_%=:\n\t"
        "}"
        :: "r"(addr), "r"(parity) : "memory");
}
// fused data+signal: store 4B into (cluster) smem and complete_tx on the
// mbarrier co-located in the SAME destination CTA. One transaction.
__device__ __forceinline__ void st_async_f32(uint32_t daddr, float v, uint32_t dmbar) {
    asm volatile("st.async.shared::cluster.mbarrier::complete_tx::bytes.f32 [%0], %1, [%2];"
                 :: "r"(daddr), "f"(v), "r"(dmbar) : "memory");
}
// branchless tanh: 1 - 2/(exp(2x)+1), ex2.approx + rcp.approx (~1e-7 abs err)
__device__ __forceinline__ float fast_tanh(float x) {
    float z = x * 2.8853900817779268f;   // 2*log2(e)
    float e;
    asm("ex2.approx.f32 %0, %1;" : "=f"(e) : "f"(z));
    float d = e + 1.0f;
    float r;
    asm("rcp.approx.f32 %0, %1;" : "=f"(r) : "f"(d));
    return fmaf(-2.0f, r, 1.0f);
}

// state buffer layout: quarter q (64 cols) padded by 16B so the 4 per-warp
// broadcast groups (one per K-quarter) hit disjoint bank sets.
#define SBUF_STRIDE 272
__device__ __forceinline__ int sidx4(int c){ return c + ((c >> 6) << 2); }

// ============================================================
// Phase 1: g_h[b][t][u] = sum_f inputs[b,t,f] * R[f,u]
// ============================================================
__global__ __launch_bounds__(256)
void p1_gemm(const float* __restrict__ x, const float* __restrict__ R) {
    extern __shared__ unsigned char smraw[];
    float* xs = (float*)smraw;                                          // 32KB
    unsigned long long* Rp = (unsigned long long*)(smraw + 64*128*4);   // 64KB

    const int tid = threadIdx.x;
    const int c = blockIdx.x;
    const int rowblk = c >> 1, uh = c & 1;
    const int m0 = rowblk * 64, ub = uh * 128;

    {
        const float4* xg = (const float4*)(x + (size_t)m0 * FDIM);
        float4* xs4 = (float4*)xs;
        #pragma unroll
        for (int i = 0; i < 8; i++) xs4[tid + 256*i] = xg[tid + 256*i];
    }
    for (int i = tid; i < 64*128; i += 256) {
        int k2 = i >> 7; int u = (i & 127) + ub;
        Rp[i] = packf2(R[(size_t)(2*k2) * UDIM + u], R[(size_t)(2*k2+1) * UDIM + u]);
    }
    __syncthreads();

    const int cg = tid & 31, tr = tid >> 5;
    const int u0 = cg * 4, r0 = tr * 8;

    unsigned long long acc[8][4];
    #pragma unroll
    for (int a = 0; a < 8; a++)
        #pragma unroll
        for (int bb = 0; bb < 4; bb++) acc[a][bb] = 0ULL;

    #pragma unroll 8
    for (int k2 = 0; k2 < 64; k2++) {
        const ulonglong2* rp2 = (const ulonglong2*)(Rp + k2*128 + u0);
        ulonglong2 v0 = rp2[0], v1 = rp2[1];
        #pragma unroll
        for (int rr = 0; rr < 8; rr++) {
            unsigned long long xp = *(const unsigned long long*)(xs + (r0+rr)*FDIM + 2*k2);
            fma2(acc[rr][0], xp, v0.x);
            fma2(acc[rr][1], xp, v0.y);
            fma2(acc[rr][2], xp, v1.x);
            fma2(acc[rr][3], xp, v1.y);
        }
    }

    #pragma unroll
    for (int rr = 0; rr < 8; rr++) {
        int m = m0 + r0 + rr;   // m = b*1024 + t -> [B][T][U] directly
        float4 o;
        o.x = lo32(acc[rr][0]) + hi32(acc[rr][0]);
        o.y = lo32(acc[rr][1]) + hi32(acc[rr][1]);
        o.z = lo32(acc[rr][2]) + hi32(acc[rr][2]);
        o.w = lo32(acc[rr][3]) + hi32(acc[rr][3]);
        *(float4*)(g_h + (size_t)m * UDIM + ub + u0) = o;
    }
}

// ============================================================
// Phase 2: recurrence, 2-batch pipeline with CROSS-BATCH ILP OVERLAP.
// 32 clusters x 2 CTAs (R12 config, proven best); cluster c handles batches
// 2c, 2c+1. Loop body ordering (the change vs R12):
//   wait_b0 -> arm -> LDS+FMA b0
//   wait_b1 (in b0's FMA shadow; fast-path) -> arm -> LDS+FMA b1
//   tail b0 (shfl/tanh/fire)  [latencies hide under b1's FMA drain]
//   tail b1 (shfl/tanh/fire) -> outputs
// Protocol unchanged: per-batch mbarrier, fused st.async, parity t&1,
// phase-0 bootstrap arrive, cta-scope acquire.
// ============================================================
__global__ __launch_bounds__(256, 1) __cluster_dims__(2, 1, 1)
void p2_rnn(const float* __restrict__ W, const float* __restrict__ bias,
            const float* __restrict__ x0, float* __restrict__ out) {
    __shared__ __align__(16) float sbuf[2][2][SBUF_STRIDE];  // [batch][parity][state]
    __shared__ __align__(8) unsigned long long mbar[2];

    const int tid  = threadIdx.x;
    uint32_t rank;
    asm("mov.u32 %0, %%cluster_ctarank;" : "=r"(rank));
    const int c    = blockIdx.x >> 1;       // cluster index
    const int b0   = 2 * c, b1 = 2 * c + 1;
    const int w    = tid >> 5;
    const int l    = tid & 31;
    const int jA   = w * 16 + (l & 7);
    const int jgA  = (int)rank * 128 + jA;
    const int jgB  = jgA + 8;
    const int k0   = (l >> 3) * 64;

    // W segments for 2 columns x quarter-K, packed f32x2: 64 u64 = 128 regs
    unsigned long long wpA[32], wpB[32];
    #pragma unroll
    for (int m = 0; m < 32; m++) {
        wpA[m] = packf2(W[(size_t)(k0 + 2*m)     * UDIM + jgA],
                        W[(size_t)(k0 + 2*m + 1) * UDIM + jgA]);
        wpB[m] = packf2(W[(size_t)(k0 + 2*m)     * UDIM + jgB],
                        W[(size_t)(k0 + 2*m + 1) * UDIM + jgB]);
    }

    const float* hA_0 = g_h + (size_t)b0 * T_STEPS * UDIM + jgA;
    const float* hB_0 = g_h + (size_t)b0 * T_STEPS * UDIM + jgB;
    const float* hA_1 = g_h + (size_t)b1 * T_STEPS * UDIM + jgA;
    const float* hB_1 = g_h + (size_t)b1 * T_STEPS * UDIM + jgB;
    float* oA_0 = out + (size_t)b0 * UDIM + jgA;
    float* oB_0 = out + (size_t)b0 * UDIM + jgB;
    float* oA_1 = out + (size_t)b1 * UDIM + jgA;
    float* oB_1 = out + (size_t)b1 * UDIM + jgB;
    const float biasA = bias[jgA];
    const float biasB = bias[jgB];
    float hA0_0 = hA_0[0], hA1_0 = hA_0[UDIM];
    float hB0_0 = hB_0[0], hB1_0 = hB_0[UDIM];
    float hA0_1 = hA_1[0], hA1_1 = hA_1[UDIM];
    float hB0_1 = hB_1[0], hB1_1 = hB_1[UDIM];

    if (tid < UDIM) {
        float v = x0[tid];
        sbuf[0][0][sidx4(tid)] = v;
        sbuf[1][0][sidx4(tid)] = v;
    }
    if (tid == 0) {
        mbar_init(smem_u32(&mbar[0]), 1);
        mbar_init(smem_u32(&mbar[1]), 1);
        mbar_arrive_plain(smem_u32(&mbar[0]));   // complete phase 0
        mbar_arrive_plain(smem_u32(&mbar[1]));
    }
    __syncthreads();
    asm volatile("barrier.cluster.arrive.aligned;" ::: "memory");
    asm volatile("barrier.cluster.wait.aligned;"   ::: "memory");

    const uint32_t m0loc = smem_u32(&mbar[0]);
    const uint32_t m1loc = smem_u32(&mbar[1]);
    const uint32_t pr    = rank ^ 1u;
    const uint32_t omb0  = mapa_u32(m0loc, rank);
    const uint32_t pmb0  = mapa_u32(m0loc, pr);
    const uint32_t omb1  = mapa_u32(m1loc, rank);
    const uint32_t pmb1  = mapa_u32(m1loc, pr);
    uint32_t osb[2][2], psb[2][2];   // [batch][parity]
    #pragma unroll
    for (int bb = 0; bb < 2; bb++) {
        osb[bb][0] = mapa_u32(smem_u32(&sbuf[bb][0][0]), rank);
        osb[bb][1] = mapa_u32(smem_u32(&sbuf[bb][1][0]), rank);
        psb[bb][0] = mapa_u32(smem_u32(&sbuf[bb][0][0]), pr);
        psb[bb][1] = mapa_u32(smem_u32(&sbuf[bb][1][0]), pr);
    }
    const uint32_t offA = (uint32_t)sidx4(jgA) * 4u;
    const uint32_t offB = (uint32_t)sidx4(jgB) * 4u;

    #pragma unroll 2
    for (int t = 0; t < T_STEPS; t++) {
        const int p = t & 1, np = p ^ 1;
        const uint32_t par = (uint32_t)(t & 1);

        // prefetch h for t+2 (independent of the chain)
        float hA2_0 = 0.f, hB2_0 = 0.f, hA2_1 = 0.f, hB2_1 = 0.f;
        if (t + 2 < T_STEPS) {
            hA2_0 = __ldcs(hA_0 + (size_t)(t + 2) * UDIM);
            hB2_0 = __ldcs(hB_0 + (size_t)(t + 2) * UDIM);
            hA2_1 = __ldcs(hA_1 + (size_t)(t + 2) * UDIM);
            hB2_1 = __ldcs(hB_1 + (size_t)(t + 2) * UDIM);
        }

        // ---- batch 0: wait + FMA issue burst ----
        mbar_wait(m0loc, par);
        if (tid == 0) mbar_expect_tx(m0loc, 1024);
        unsigned long long aA0_0 = 0ULL, aA1_0 = 0ULL, aB0_0 = 0ULL, aB1_0 = 0ULL;
        {
            const float* sb = &sbuf[0][p][sidx4(k0)];
            #pragma unroll
            for (int i = 0; i < 8; i++) {
                ulonglong2 s0 = *(const ulonglong2*)(sb + 8*i);
                ulonglong2 s1 = *(const ulonglong2*)(sb + 8*i + 4);
                fma2(aA0_0, s0.x, wpA[4*i + 0]);
                fma2(aB0_0, s0.x, wpB[4*i + 0]);
                fma2(aA1_0, s0.y, wpA[4*i + 1]);
                fma2(aB1_0, s0.y, wpB[4*i + 1]);
                fma2(aA0_0, s1.x, wpA[4*i + 2]);
                fma2(aB0_0, s1.x, wpB[4*i + 2]);
                fma2(aA1_0, s1.y, wpA[4*i + 3]);
                fma2(aB1_0, s1.y, wpB[4*i + 3]);
            }
        }

        // ---- batch 1: wait (in b0's FMA shadow) + FMA issue burst ----
        mbar_wait(m1loc, par);
        if (tid == 0) mbar_expect_tx(m1loc, 1024);
        unsigned long long aA0_1 = 0ULL, aA1_1 = 0ULL, aB0_1 = 0ULL, aB1_1 = 0ULL;
        {
            const float* sb = &sbuf[1][p][sidx4(k0)];
            #pragma unroll
            for (int i = 0; i < 8; i++) {
                ulonglong2 s0 = *(const ulonglong2*)(sb + 8*i);
                ulonglong2 s1 = *(const ulonglong2*)(sb + 8*i + 4);
                fma2(aA0_1, s0.x, wpA[4*i + 0]);
                fma2(aB0_1, s0.x, wpB[4*i + 0]);
                fma2(aA1_1, s0.y, wpA[4*i + 1]);
                fma2(aB1_1, s0.y, wpB[4*i + 1]);
                fma2(aA0_1, s1.x, wpA[4*i + 2]);
                fma2(aB0_1, s1.x, wpB[4*i + 2]);
                fma2(aA1_1, s1.y, wpA[4*i + 3]);
                fma2(aB1_1, s1.y, wpB[4*i + 3]);
            }
        }

        // ---- batch 0 tail: latencies hide under b1's FMA drain ----
        float valA0, valB0;
        {
            float pA = (lo32(aA0_0) + hi32(aA0_0)) + (lo32(aA1_0) + hi32(aA1_0));
            float pB = (lo32(aB0_0) + hi32(aB0_0)) + (lo32(aB1_0) + hi32(aB1_0));
            pA += __shfl_xor_sync(0xffffffffu, pA, 8);
            pB += __shfl_xor_sync(0xffffffffu, pB, 8);
            pA += __shfl_xor_sync(0xffffffffu, pA, 16);
            pB += __shfl_xor_sync(0xffffffffu, pB, 16);
            valA0 = fast_tanh(hA0_0 + pA + biasA);
            valB0 = fast_tanh(hB0_0 + pB + biasB);
        }
        if (l < 8) {
            const uint32_t ob = osb[0][np];
            st_async_f32(ob + offA, valA0, omb0);
            st_async_f32(ob + offB, valB0, omb0);
        } else if (l < 16) {
            const uint32_t pb = psb[0][np];
            st_async_f32(pb + offA, valA0, pmb0);
            st_async_f32(pb + offB, valB0, pmb0);
        }

        // ---- batch 1 tail ----
        float valA1, valB1;
        {
            float pA = (lo32(aA0_1) + hi32(aA0_1)) + (lo32(aA1_1) + hi32(aA1_1));
            float pB = (lo32(aB0_1) + hi32(aB0_1)) + (lo32(aB1_1) + hi32(aB1_1));
            pA += __shfl_xor_sync(0xffffffffu, pA, 8);
            pB += __shfl_xor_sync(0xffffffffu, pB, 8);
            pA += __shfl_xor_sync(0xffffffffu, pA, 16);
            pB += __shfl_xor_sync(0xffffffffu, pB, 16);
            valA1 = fast_tanh(hA0_1 + pA + biasA);
            valB1 = fast_tanh(hB0_1 + pB + biasB);
        }
        if (l < 8) {
            const uint32_t ob = osb[1][np];
            st_async_f32(ob + offA, valA1, omb1);
            st_async_f32(ob + offB, valB1, omb1);
        } else if (l < 16) {
            const uint32_t pb = psb[1][np];
            st_async_f32(pb + offA, valA1, pmb1);
            st_async_f32(pb + offB, valB1, pmb1);
        } else if (l < 24) {
            // outputs [T][B][U], off the inter-CTA chain
            oA_0[(size_t)t * BATCH * UDIM] = valA0;
            oA_1[(size_t)t * BATCH * UDIM] = valA1;
        } else {
            oB_0[(size_t)t * BATCH * UDIM] = valB0;
            oB_1[(size_t)t * BATCH * UDIM] = valB1;
        }

        hA0_0 = hA1_0; hA1_0 = hA2_0;
        hB0_0 = hB1_0; hB1_0 = hB2_0;
        hA0_1 = hA1_1; hA1_1 = hA2_1;
        hB0_1 = hB1_1; hB1_1 = hB2_1;
    }

    asm volatile("barrier.cluster.arrive.aligned;" ::: "memory");
    asm volatile("barrier.cluster.wait.aligned;"   ::: "memory");
}

extern "C" void kernel_launch(void* const* d_in, const int* in_sizes, int n_in,
                              void* d_out, int out_size) {
    const float* x    = (const float*)d_in[0];  // [B, T, F]
    const float* R    = (const float*)d_in[1];  // [F, U]
    const float* W    = (const float*)d_in[2];  // [U, U]
    const float* bias = (const float*)d_in[3];  // [U]
    const float* x0   = (const float*)d_in[4];  // [U]
    float* out = (float*)d_out;                 // [T, B, U]

    cudaFuncSetAttribute(p1_gemm, cudaFuncAttributeMaxDynamicSharedMemorySize, 98304);
    p1_gemm<<<2048, 256, 98304>>>(x, R);
    p2_rnn<<<64, 256>>>(W, bias, x0, out);
}